// round 16
// baseline (speedup 1.0000x reference)
#include <cuda_runtime.h>
#include <cuda_fp16.h>
#include <cstdint>

#define NN 100000
#define NPAD 100096   // 782*128, pad rows stay zero forever
#define NE 1600000
#define NG 1024
#define DD 128
#define NB_SCAN 391   // ceil(NN/256)
#define NT_TILES 782  // M tiles of 128
#define GX 148        // persistent blocks in x

// ---------------- scratch (device globals; zero-initialized at load; k_final's
// tail re-zeros deg/cursor/alloc/pool; plane pad rows are never written) -------
__device__ __half g_xH[NPAD * DD];
__device__ __half g_xL[NPAD * DD];
__device__ __half g_hH[NPAD * DD];   // h1 hi plane (gemm2 A)
__device__ __half g_hL[NPAD * DD];
__device__ __half g_yB[NPAD * DD];   // Y = src@Wl^T, fp16 (gather source)
__device__ float g_z[NN * DD];       // Z = src@Wr^T, fp32
__device__ float g_h2[NN * DD];
__device__ float g_pool[NG * DD];
// W frags fp16: [layer][j 0..31][s 0..7][lane] -> uint2 {h01, h23}
__device__ uint2 g_Wf[2 * 32 * 8 * 32];
__device__ int   g_deg[NN];
__device__ int   g_rowptr[NN];
__device__ int   g_cursor[NN];
__device__ int   g_esrc[NE];
__device__ int   g_alloc;

// ---------------- helpers ----------------
__device__ __forceinline__ uint32_t smem_to_u32(const void* p) {
    uint32_t a;
    asm("{ .reg .u64 t; cvta.to.shared.u64 t, %1; cvt.u32.u64 %0, t; }" : "=r"(a) : "l"(p));
    return a;
}
__device__ __forceinline__ uint32_t h2u(__half2 v) { return *reinterpret_cast<uint32_t*>(&v); }

#define LDM_X4(r, addr) \
    asm volatile("ldmatrix.sync.aligned.m8n8.x4.shared.b16 {%0,%1,%2,%3}, [%4];" \
        : "=r"((r)[0]), "=r"((r)[1]), "=r"((r)[2]), "=r"((r)[3]) : "r"(addr))

#define MMA_F16(c, b0, b1, a) \
    asm volatile("mma.sync.aligned.m16n8k16.row.col.f32.f16.f16.f32 " \
        "{%0,%1,%2,%3}, {%4,%5,%6,%7}, {%8,%9}, {%0,%1,%2,%3};" \
        : "+f"((c)[0]), "+f"((c)[1]), "+f"((c)[2]), "+f"((c)[3]) \
        : "r"((a)[0]), "r"((a)[1]), "r"((a)[2]), "r"((a)[3]), "r"(b0), "r"(b1))

#define CP_ASYNC16(dst, src) \
    asm volatile("cp.async.cg.shared.global [%0], [%1], 16;" :: "r"(dst), "l"(src))
#define CP_COMMIT() asm volatile("cp.async.commit_group;" ::: "memory")
#define CP_WAIT(n)  asm volatile("cp.async.wait_group %0;" :: "n"(n) : "memory")

// ---------------- slot 0: prep (x->fp16 hi/lo planes, W fp16 frags) + degree ----
#define PREP_XB_BLKS 12500   // NN*DD/4 / 256
#define PREP_WF_BLKS 64      // 2*32*8*32 / 256
__global__ void k_prep_deg(const float* __restrict__ x,
                           const float* __restrict__ W1l, const float* __restrict__ W1r,
                           const float* __restrict__ W2l, const float* __restrict__ W2r,
                           const int* __restrict__ dst) {
    if (blockIdx.x < PREP_XB_BLKS) {
        int i = blockIdx.x * 256 + threadIdx.x;
        float4 f = ((const float4*)x)[i];
        __half2 h01 = __floats2half2_rn(f.x, f.y);
        __half2 h23 = __floats2half2_rn(f.z, f.w);
        __half2 l01 = __floats2half2_rn(f.x - __low2float(h01), f.y - __high2float(h01));
        __half2 l23 = __floats2half2_rn(f.z - __low2float(h23), f.w - __high2float(h23));
        ((uint2*)g_xH)[i] = make_uint2(h2u(h01), h2u(h23));
        ((uint2*)g_xL)[i] = make_uint2(h2u(l01), h2u(l23));
        return;
    }
    if (blockIdx.x < PREP_XB_BLKS + PREP_WF_BLKS) {
        int i = (blockIdx.x - PREP_XB_BLKS) * 256 + threadIdx.x;   // 0 .. 16383
        int lane = i & 31;
        int s = (i >> 5) & 7;
        int j = (i >> 8) & 31;
        int layer = i >> 13;
        int n = (j & 15) * 8 + (lane >> 2);
        int k = s * 16 + (lane & 3) * 2;
        const float* Wl = layer ? W2l : W1l;
        const float* Wr = layer ? W2r : W1r;
        const float* W = (j < 16) ? Wl : Wr;
        float w[4];
#pragma unroll
        for (int q = 0; q < 4; q++) {
            int kk = k + (q >> 1) * 8 + (q & 1);
            w[q] = W[n * DD + kk];
        }
        __half2 h01 = __floats2half2_rn(w[0], w[1]);
        __half2 h23 = __floats2half2_rn(w[2], w[3]);
        g_Wf[i] = make_uint2(h2u(h01), h2u(h23));
        return;
    }
    int i = (blockIdx.x - PREP_XB_BLKS - PREP_WF_BLKS) * 256 + threadIdx.x;
    if (i < NE) atomicAdd(&g_deg[dst[i]], 1);
}

// ---------------- slot 1: bucket allocation ----------------
__global__ void k_alloc() {
    __shared__ int s[256];
    __shared__ int base;
    int b = blockIdx.x, t = threadIdx.x;
    int i = b * 256 + t;
    int v = (i < NN) ? g_deg[i] : 0;
    s[t] = v;
    __syncthreads();
#pragma unroll
    for (int off = 1; off < 256; off <<= 1) {
        int add = (t >= off) ? s[t - off] : 0;
        __syncthreads();
        s[t] += add;
        __syncthreads();
    }
    if (t == 255) base = atomicAdd(&g_alloc, s[255]);
    __syncthreads();
    if (i < NN) g_rowptr[i] = base + s[t] - v;
}

// ---------------- slot 2: scatter edges into buckets ----------------
__global__ void k_scatter(const int* __restrict__ src, const int* __restrict__ dst) {
    int i = blockIdx.x * blockDim.x + threadIdx.x;
    if (i >= NE) return;
    int d = dst[i];
    int pos = atomicAdd(&g_cursor[d], 1);
    g_esrc[g_rowptr[d] + pos] = src[i];
}

// ---------------- slot 3 (PROFILED): persistent GEMM [Y|Z] = A @ [Wl;Wr]^T ------
// Grid (148, 2): each CTA loops over ~5-6 M-tiles. W staged once per CTA.
// A chunk ring (2 chunks x 2 planes) pipelines ACROSS tiles: chunk i+2's cp.async
// overlaps chunk i+1's MMA. fp16 2-term split.
#define SA_STRIDE 72
#define SA_CHUNK (128 * SA_STRIDE)                 // fp16 elems per plane-chunk
#define SW_OFF   (4 * SA_CHUNK * 2)                // byte offset of W region
#define SW_BYTES (16 * 8 * 32 * 8)                 // 32KB
#define SMEM_GEMM (SW_OFF + SW_BYTES)
__global__ void __launch_bounds__(256, 2)
k_gemm(const __half* __restrict__ AH, const __half* __restrict__ AL,
       const uint2* __restrict__ Wf,
       __half* __restrict__ yB, float* __restrict__ z) {
    extern __shared__ __align__(16) __half sA[];
    int tid = threadIdx.x;
    int wid = tid >> 5, lane = tid & 31;
    int wm = wid & 3, wn = wid >> 2;
    int jbase = blockIdx.y * 16;

    int frow = tid >> 1, fhalf = tid & 1;
    int g = lane >> 3, ri = lane & 7;
    uint32_t sbase = smem_to_u32(sA);
    uint32_t swbase = sbase + SW_OFF;

    // issue chunk (tile t, half c) copy into ring slot sl
    auto issueA = [&](int t, int c, int sl) {
#pragma unroll
        for (int p = 0; p < 2; p++) {
            const __half* gsrc = (p ? AL : AH)
                + (size_t)(t * 128 + frow) * DD + c * 64 + fhalf * 32;
            uint32_t sdst = sbase
                + (uint32_t)((sl * 2 + p) * SA_CHUNK + frow * SA_STRIDE + fhalf * 32) * 2;
#pragma unroll
            for (int q = 0; q < 4; q++)
                CP_ASYNC16(sdst + q * 16, (const char*)(gsrc + q * 8));
        }
    };

    int t0 = blockIdx.x;
    // prologue: G0 = {W stage, chunk0}, G1 = {chunk1}
    {
        const char* wsrc = (const char*)(Wf + jbase * 256);
#pragma unroll
        for (int q = 0; q < 8; q++) {
            uint32_t off = (uint32_t)(tid * 16 + q * 4096);
            CP_ASYNC16(swbase + off, wsrc + off);
        }
        issueA(t0, 0, 0);
        CP_COMMIT();
        issueA(t0, 1, 1);
        CP_COMMIT();
    }

    float acc[2][8][4];
#pragma unroll
    for (int a = 0; a < 2; a++)
#pragma unroll
        for (int b = 0; b < 8; b++)
#pragma unroll
            for (int q = 0; q < 4; q++) acc[a][b][q] = 0.f;

    int r_in = lane >> 2;
    int n_in = (lane & 3) * 2;
    bool isY = (blockIdx.y == 0);

#pragma unroll 1
    for (int i = 0; ; i++) {
        int t = t0 + (i >> 1) * GX;
        if (t >= NT_TILES) break;
        int c = i & 1;
        int sl = i & 1;          // ring slot (2 chunk slots)
        // chunk i+1 exists iff (tile of i+1) < NT_TILES
        int tn = t0 + ((i + 1) >> 1) * GX;
        if (tn < NT_TILES) CP_WAIT(1); else CP_WAIT(0);
        __syncthreads();

        uint32_t sAh_u = sbase + (uint32_t)(sl * 2 + 0) * SA_CHUNK * 2;
        uint32_t sAl_u = sbase + (uint32_t)(sl * 2 + 1) * SA_CHUNK * 2;

#pragma unroll
        for (int ss = 0; ss < 4; ss++) {
            int s = c * 4 + ss;
            int k0 = ss * 16;
            uint32_t Ah[2][4], Al[2][4];
#pragma unroll
            for (int mt = 0; mt < 2; mt++) {
                uint32_t row = (uint32_t)(wm * 32 + mt * 16 + (g & 1) * 8 + ri);
                uint32_t byo = (row * SA_STRIDE + (uint32_t)(k0 + (g >> 1) * 8)) * 2;
                LDM_X4(Ah[mt], sAh_u + byo);
                LDM_X4(Al[mt], sAl_u + byo);
            }
#pragma unroll
            for (int g4 = 0; g4 < 2; g4++) {
                uint2 wv[4];
#pragma unroll
                for (int q = 0; q < 4; q++) {
                    int jj = wn * 8 + g4 * 4 + q;
                    uint32_t off = (uint32_t)(((jj * 8 + s) << 5) + lane) * 8;
                    asm volatile("ld.shared.v2.u32 {%0,%1}, [%2];"
                        : "=r"(wv[q].x), "=r"(wv[q].y) : "r"(swbase + off));
                }
#pragma unroll
                for (int q = 0; q < 4; q++) {
                    int nt = g4 * 4 + q;
                    MMA_F16(acc[0][nt], wv[q].x, wv[q].y, Ah[0]);
                    MMA_F16(acc[1][nt], wv[q].x, wv[q].y, Ah[1]);
                }
#pragma unroll
                for (int q = 0; q < 4; q++) {
                    int nt = g4 * 4 + q;
                    MMA_F16(acc[0][nt], wv[q].x, wv[q].y, Al[0]);
                    MMA_F16(acc[1][nt], wv[q].x, wv[q].y, Al[1]);
                }
            }
        }
        __syncthreads();   // slot sl free for chunk i+2

        // issue chunk i+2 (overlaps chunk i+1's MMA next iteration)
        int t2 = t0 + ((i + 2) >> 1) * GX;
        if (t2 < NT_TILES) {
            issueA(t2, (i + 2) & 1, sl);
            CP_COMMIT();
        }

        if (c == 1) {
            // epilogue for tile t
            int m0 = t * 128;
#pragma unroll
            for (int nt = 0; nt < 8; nt++) {
                int n = wn * 64 + nt * 8 + n_in;
#pragma unroll
                for (int mt = 0; mt < 2; mt++) {
                    int r0 = m0 + wm * 32 + mt * 16 + r_in;
                    if (r0 < NN) {
                        if (isY) {
                            __half2 o = __floats2half2_rn(acc[mt][nt][0], acc[mt][nt][1]);
                            *(uint32_t*)(yB + (size_t)r0 * DD + n) = h2u(o);
                        } else {
                            *(float2*)(z + (size_t)r0 * DD + n) =
                                make_float2(acc[mt][nt][0], acc[mt][nt][1]);
                        }
                    }
                    int r1 = r0 + 8;
                    if (r1 < NN) {
                        if (isY) {
                            __half2 o = __floats2half2_rn(acc[mt][nt][2], acc[mt][nt][3]);
                            *(uint32_t*)(yB + (size_t)r1 * DD + n) = h2u(o);
                        } else {
                            *(float2*)(z + (size_t)r1 * DD + n) =
                                make_float2(acc[mt][nt][2], acc[mt][nt][3]);
                        }
                    }
                }
            }
            // reset accumulators for next tile
#pragma unroll
            for (int a = 0; a < 2; a++)
#pragma unroll
                for (int b = 0; b < 8; b++)
#pragma unroll
                    for (int q = 0; q < 4; q++) acc[a][b][q] = 0.f;
        }
    }
}

// ---------------- fused agg + epilogue: h = relu(mean_nb(Y) + Z + bias) ----------
__global__ void k_aggf(const float* __restrict__ z, const float* __restrict__ bias,
                       __half* __restrict__ outH, __half* __restrict__ outL,
                       float* __restrict__ outF) {
    int w = (blockIdx.x * blockDim.x + threadIdx.x) >> 5;
    int lane = threadIdx.x & 31;
    if (w >= NN) return;
    int beg = g_rowptr[w];
    int dcnt = g_deg[w];
    int end = beg + dcnt;
    const uint2* in2 = (const uint2*)g_yB;
    float a0 = 0.f, a1 = 0.f, a2 = 0.f, a3 = 0.f;
    int e = beg;
#pragma unroll 1
    for (; e + 7 < end; e += 8) {
        int s0 = __ldg(&g_esrc[e]);
        int s1 = __ldg(&g_esrc[e + 1]);
        int s2 = __ldg(&g_esrc[e + 2]);
        int s3 = __ldg(&g_esrc[e + 3]);
        int s4 = __ldg(&g_esrc[e + 4]);
        int s5 = __ldg(&g_esrc[e + 5]);
        int s6 = __ldg(&g_esrc[e + 6]);
        int s7 = __ldg(&g_esrc[e + 7]);
        uint2 v0 = __ldg(&in2[(size_t)s0 * 32 + lane]);
        uint2 v1 = __ldg(&in2[(size_t)s1 * 32 + lane]);
        uint2 v2 = __ldg(&in2[(size_t)s2 * 32 + lane]);
        uint2 v3 = __ldg(&in2[(size_t)s3 * 32 + lane]);
        uint2 v4 = __ldg(&in2[(size_t)s4 * 32 + lane]);
        uint2 v5 = __ldg(&in2[(size_t)s5 * 32 + lane]);
        uint2 v6 = __ldg(&in2[(size_t)s6 * 32 + lane]);
        uint2 v7 = __ldg(&in2[(size_t)s7 * 32 + lane]);
#pragma unroll
        for (int q = 0; q < 8; q++) {
            uint2 v = q == 0 ? v0 : q == 1 ? v1 : q == 2 ? v2 : q == 3 ? v3
                    : q == 4 ? v4 : q == 5 ? v5 : q == 6 ? v6 : v7;
            float2 p0 = __half22float2(*(__half2*)&v.x);
            float2 p1 = __half22float2(*(__half2*)&v.y);
            a0 += p0.x; a1 += p0.y; a2 += p1.x; a3 += p1.y;
        }
    }
    for (; e < end; e++) {
        int s0 = __ldg(&g_esrc[e]);
        uint2 v = __ldg(&in2[(size_t)s0 * 32 + lane]);
        float2 p0 = __half22float2(*(__half2*)&v.x);
        float2 p1 = __half22float2(*(__half2*)&v.y);
        a0 += p0.x; a1 += p0.y; a2 += p1.x; a3 += p1.y;
    }
    float inv = (dcnt > 0) ? 1.0f / (float)dcnt : 0.0f;
    float4 zz = ((const float4*)z)[w * 32 + lane];
    float4 bb = ((const float4*)bias)[lane];
    float f0 = fmaxf(a0 * inv + zz.x + bb.x, 0.f);
    float f1 = fmaxf(a1 * inv + zz.y + bb.y, 0.f);
    float f2 = fmaxf(a2 * inv + zz.z + bb.z, 0.f);
    float f3 = fmaxf(a3 * inv + zz.w + bb.w, 0.f);
    if (outF) {
        ((float4*)outF)[w * 32 + lane] = make_float4(f0, f1, f2, f3);
    } else {
        __half2 h01 = __floats2half2_rn(f0, f1);
        __half2 h23 = __floats2half2_rn(f2, f3);
        __half2 l01 = __floats2half2_rn(f0 - __low2float(h01), f1 - __high2float(h01));
        __half2 l23 = __floats2half2_rn(f2 - __low2float(h23), f3 - __high2float(h23));
        ((uint2*)outH)[w * 32 + lane] = make_uint2(h2u(h01), h2u(h23));
        ((uint2*)outL)[w * 32 + lane] = make_uint2(h2u(l01), h2u(l23));
    }
}

// ---------------- global add pool (batch is sorted, int32) ----------------
#define NPB 256
__global__ void k_pool(const float* __restrict__ h, const int* __restrict__ batch) {
    int t = threadIdx.x;
    int start = blockIdx.x * NPB;
    int end = start + NPB; if (end > NN) end = NN;
    if (start >= NN) return;
    int cur = batch[start];
    float sum = 0.f;
    for (int i = start; i < end; i++) {
        int b = __ldg(&batch[i]);
        if (b != cur) {
            atomicAdd(&g_pool[cur * DD + t], sum);
            sum = 0.f; cur = b;
        }
        sum += h[(size_t)i * DD + t];
    }
    atomicAdd(&g_pool[cur * DD + t], sum);
}

// ---------------- LayerNorm + final linear + scratch re-zero ----------------
__global__ void k_final(const float* __restrict__ ln_g, const float* __restrict__ ln_b,
                        const float* __restrict__ Wlin, const float* __restrict__ blin,
                        float* __restrict__ out) {
    int gtid = blockIdx.x * blockDim.x + threadIdx.x;
    int w = gtid >> 5;
    int lane = threadIdx.x & 31;
    if (w < NG) {
        float4 v = ((const float4*)g_pool)[w * 32 + lane];
        float s = v.x + v.y + v.z + v.w;
#pragma unroll
        for (int o = 16; o; o >>= 1) s += __shfl_xor_sync(0xffffffffu, s, o);
        float mean = s * (1.0f / 128.0f);
        float dx = v.x - mean, dy = v.y - mean, dz = v.z - mean, dw = v.w - mean;
        float q = dx * dx + dy * dy + dz * dz + dw * dw;
#pragma unroll
        for (int o = 16; o; o >>= 1) q += __shfl_xor_sync(0xffffffffu, q, o);
        float var = q * (1.0f / 128.0f);
        float r = rsqrtf(var + 1e-5f);
        float4 gg = ((const float4*)ln_g)[lane];
        float4 bb = ((const float4*)ln_b)[lane];
        float n0 = dx * r * gg.x + bb.x;
        float n1 = dy * r * gg.y + bb.y;
        float n2 = dz * r * gg.z + bb.z;
        float n3 = dw * r * gg.w + bb.w;
        float4 w0 = ((const float4*)Wlin)[lane];
        float4 w1 = ((const float4*)Wlin)[32 + lane];
        float d0 = n0 * w0.x + n1 * w0.y + n2 * w0.z + n3 * w0.w;
        float d1 = n0 * w1.x + n1 * w1.y + n2 * w1.z + n3 * w1.w;
#pragma unroll
        for (int o = 16; o; o >>= 1) {
            d0 += __shfl_xor_sync(0xffffffffu, d0, o);
            d1 += __shfl_xor_sync(0xffffffffu, d1, o);
        }
        if (lane == 0) {
            out[w * 2 + 0] = d0 + blin[0];
            out[w * 2 + 1] = d1 + blin[1];
        }
        ((float4*)g_pool)[w * 32 + lane] = make_float4(0.f, 0.f, 0.f, 0.f);
    }
    if (gtid == 0) g_alloc = 0;
    for (int i = gtid; i < NN; i += NG * 32) { g_deg[i] = 0; g_cursor[i] = 0; }
}

// ---------------- launch ----------------
extern "C" void kernel_launch(void* const* d_in, const int* in_sizes, int n_in,
                              void* d_out, int out_size) {
    const float* x     = (const float*)d_in[0];
    const int*   ei    = (const int*)d_in[1];
    const int*   bat   = (const int*)d_in[2];
    const float* W1l   = (const float*)d_in[3];
    const float* b1l   = (const float*)d_in[4];
    const float* W1r   = (const float*)d_in[5];
    const float* W2l   = (const float*)d_in[6];
    const float* b2l   = (const float*)d_in[7];
    const float* W2r   = (const float*)d_in[8];
    const float* ln_g  = (const float*)d_in[9];
    const float* ln_b  = (const float*)d_in[10];
    const float* Wlin  = (const float*)d_in[11];
    const float* blin  = (const float*)d_in[12];

    const int* src = ei;
    const int* dst = ei + NE;

    __half *xH, *xL, *hH, *hL, *yB;
    float *z, *h2;
    uint2* wf;
    cudaGetSymbolAddress((void**)&xH, g_xH);
    cudaGetSymbolAddress((void**)&xL, g_xL);
    cudaGetSymbolAddress((void**)&hH, g_hH);
    cudaGetSymbolAddress((void**)&hL, g_hL);
    cudaGetSymbolAddress((void**)&yB, g_yB);
    cudaGetSymbolAddress((void**)&z,  g_z);
    cudaGetSymbolAddress((void**)&h2, g_h2);
    cudaGetSymbolAddress((void**)&wf, g_Wf);

    cudaFuncSetAttribute(k_gemm, cudaFuncAttributeMaxDynamicSharedMemorySize, SMEM_GEMM);

    int degblks = (NE + 255) / 256;
    k_prep_deg<<<PREP_XB_BLKS + PREP_WF_BLKS + degblks, 256>>>(x, W1l, W1r, W2l, W2r, dst);  // 0
    k_alloc<<<NB_SCAN, 256>>>();                                                              // 1
    k_scatter<<<degblks, 256>>>(src, dst);                                                    // 2

    const int LSTRIDE = 32 * 8 * 32;   // uint2 per layer
    dim3 ggrid(GX, 2);
    k_gemm<<<ggrid, 256, SMEM_GEMM>>>(xH, xL, wf, yB, z);                                     // 3 (profiled)
    k_aggf<<<(NN * 32 + 255) / 256, 256>>>(z, b1l, hH, hL, (float*)nullptr);                  // 4
    k_gemm<<<ggrid, 256, SMEM_GEMM>>>(hH, hL, wf + LSTRIDE, yB, z);                           // 5
    k_aggf<<<(NN * 32 + 255) / 256, 256>>>(z, b2l, (__half*)nullptr,
                                           (__half*)nullptr, h2);                             // 6

    k_pool<<<(NN + NPB - 1) / NPB, 128>>>(h2, bat);                                           // 7
    k_final<<<(NG * 32 + 255) / 256, 256>>>(ln_g, ln_b, Wlin, blin, (float*)d_out);           // 8
}

// round 17
// speedup vs baseline: 1.1852x; 1.1852x over previous
#include <cuda_runtime.h>
#include <cuda_fp16.h>
#include <cstdint>

#define NN 100000
#define NPAD 100096   // 782*128, pad rows stay zero forever
#define NE 1600000
#define NG 1024
#define DD 128
#define NB_SCAN 391   // ceil(NN/256)

// ---------------- scratch (device globals; zero-initialized at load; k_final's
// tail re-zeros deg/cursor/alloc/pool; plane pad rows are never written) -------
__device__ __half g_xA[NPAD * DD];   // fp16 x (gemm1 A)
__device__ __half g_hA[NPAD * DD];   // fp16 h1 (gemm2 A)
__device__ __half g_yB[NPAD * DD];   // Y = src@Wl^T, fp16 (gather source)
__device__ float g_z[NN * DD];       // Z = src@Wr^T, fp32
__device__ float g_h2[NN * DD];
__device__ float g_pool[NG * DD];
// W frags fp16: [layer][j 0..31][s 0..7][lane] -> uint2 {h01, h23}
__device__ uint2 g_Wf[2 * 32 * 8 * 32];
__device__ int   g_deg[NN];
__device__ int   g_rowptr[NN];
__device__ int   g_cursor[NN];
__device__ int   g_esrc[NE];
__device__ int   g_alloc;

// ---------------- helpers ----------------
__device__ __forceinline__ uint32_t smem_to_u32(const void* p) {
    uint32_t a;
    asm("{ .reg .u64 t; cvta.to.shared.u64 t, %1; cvt.u32.u64 %0, t; }" : "=r"(a) : "l"(p));
    return a;
}
__device__ __forceinline__ uint32_t h2u(__half2 v) { return *reinterpret_cast<uint32_t*>(&v); }

#define LDM_X4(r, addr) \
    asm volatile("ldmatrix.sync.aligned.m8n8.x4.shared.b16 {%0,%1,%2,%3}, [%4];" \
        : "=r"((r)[0]), "=r"((r)[1]), "=r"((r)[2]), "=r"((r)[3]) : "r"(addr))

#define MMA_F16(c, b0, b1, a) \
    asm volatile("mma.sync.aligned.m16n8k16.row.col.f32.f16.f16.f32 " \
        "{%0,%1,%2,%3}, {%4,%5,%6,%7}, {%8,%9}, {%0,%1,%2,%3};" \
        : "+f"((c)[0]), "+f"((c)[1]), "+f"((c)[2]), "+f"((c)[3]) \
        : "r"((a)[0]), "r"((a)[1]), "r"((a)[2]), "r"((a)[3]), "r"(b0), "r"(b1))

#define CP_ASYNC16(dst, src) \
    asm volatile("cp.async.cg.shared.global [%0], [%1], 16;" :: "r"(dst), "l"(src))
#define CP_COMMIT() asm volatile("cp.async.commit_group;" ::: "memory")
#define CP_WAIT(n)  asm volatile("cp.async.wait_group %0;" :: "n"(n) : "memory")

// ---------------- slot 0: prep (x->fp16 plane, W fp16 frags) + degree ----------
#define PREP_XB_BLKS 12500   // NN*DD/4 / 256
#define PREP_WF_BLKS 64      // 2*32*8*32 / 256
__global__ void k_prep_deg(const float* __restrict__ x,
                           const float* __restrict__ W1l, const float* __restrict__ W1r,
                           const float* __restrict__ W2l, const float* __restrict__ W2r,
                           const int* __restrict__ dst) {
    if (blockIdx.x < PREP_XB_BLKS) {
        int i = blockIdx.x * 256 + threadIdx.x;
        float4 f = ((const float4*)x)[i];
        __half2 h01 = __floats2half2_rn(f.x, f.y);
        __half2 h23 = __floats2half2_rn(f.z, f.w);
        ((uint2*)g_xA)[i] = make_uint2(h2u(h01), h2u(h23));
        return;
    }
    if (blockIdx.x < PREP_XB_BLKS + PREP_WF_BLKS) {
        int i = (blockIdx.x - PREP_XB_BLKS) * 256 + threadIdx.x;   // 0 .. 16383
        int lane = i & 31;
        int s = (i >> 5) & 7;         // k-step 0..7 (K=128)
        int j = (i >> 8) & 31;        // n-tile 0..31 (N=256: j<16 -> Wl, else Wr)
        int layer = i >> 13;
        int n = (j & 15) * 8 + (lane >> 2);
        int k = s * 16 + (lane & 3) * 2;
        const float* Wl = layer ? W2l : W1l;
        const float* Wr = layer ? W2r : W1r;
        const float* W = (j < 16) ? Wl : Wr;
        float w[4];
#pragma unroll
        for (int q = 0; q < 4; q++) {
            int kk = k + (q >> 1) * 8 + (q & 1);
            w[q] = W[n * DD + kk];
        }
        __half2 h01 = __floats2half2_rn(w[0], w[1]);
        __half2 h23 = __floats2half2_rn(w[2], w[3]);
        g_Wf[i] = make_uint2(h2u(h01), h2u(h23));
        return;
    }
    int i = (blockIdx.x - PREP_XB_BLKS - PREP_WF_BLKS) * 256 + threadIdx.x;
    if (i < NE) atomicAdd(&g_deg[dst[i]], 1);
}

// ---------------- slot 1: bucket allocation ----------------
__global__ void k_alloc() {
    __shared__ int s[256];
    __shared__ int base;
    int b = blockIdx.x, t = threadIdx.x;
    int i = b * 256 + t;
    int v = (i < NN) ? g_deg[i] : 0;
    s[t] = v;
    __syncthreads();
#pragma unroll
    for (int off = 1; off < 256; off <<= 1) {
        int add = (t >= off) ? s[t - off] : 0;
        __syncthreads();
        s[t] += add;
        __syncthreads();
    }
    if (t == 255) base = atomicAdd(&g_alloc, s[255]);
    __syncthreads();
    if (i < NN) g_rowptr[i] = base + s[t] - v;
}

// ---------------- slot 2: scatter edges into buckets ----------------
__global__ void k_scatter(const int* __restrict__ src, const int* __restrict__ dst) {
    int i = blockIdx.x * blockDim.x + threadIdx.x;
    if (i >= NE) return;
    int d = dst[i];
    int pos = atomicAdd(&g_cursor[d], 1);
    g_esrc[g_rowptr[d] + pos] = src[i];
}

// ---------------- slot 3 (PROFILED): GEMM  [Y|Z] = A @ [Wl;Wr]^T ----------------
// Single fp16 A plane (no split). A double-buffered via cp.async; W half (32KB)
// staged in SMEM once per block. 8 independent MMAs per n-tile group.
#define SA_STRIDE 72
#define SA_CHUNK (128 * SA_STRIDE)                 // fp16 elems per chunk
#define SW_OFF   (2 * SA_CHUNK * 2)                // byte offset of W region (36KB)
#define SW_BYTES (16 * 8 * 32 * 8)                 // 32KB
#define SMEM_GEMM (SW_OFF + SW_BYTES)
__global__ void __launch_bounds__(256, 2)
k_gemm(const __half* __restrict__ A,
       const uint2* __restrict__ Wf,
       __half* __restrict__ yB, float* __restrict__ z) {
    extern __shared__ __align__(16) __half sA[];   // [chunk][SA_CHUNK] then W
    int tid = threadIdx.x;
    int wid = tid >> 5, lane = tid & 31;
    int m0 = blockIdx.x * 128;
    int wm = wid & 3, wn = wid >> 2;
    int jbase = blockIdx.y * 16;

    float acc[2][8][4];
#pragma unroll
    for (int a = 0; a < 2; a++)
#pragma unroll
        for (int b = 0; b < 8; b++)
#pragma unroll
            for (int q = 0; q < 4; q++) acc[a][b][q] = 0.f;

    int frow = tid >> 1, fhalf = tid & 1;   // plane pad rows are zero -> no guard
    int g = lane >> 3, ri = lane & 7;
    uint32_t sbase = smem_to_u32(sA);
    uint32_t swbase = sbase + SW_OFF;

    // ---- group 0: W half (32KB contiguous) + A chunk 0 ----
    {
        const char* wsrc = (const char*)(Wf + jbase * 256);
#pragma unroll
        for (int q = 0; q < 8; q++) {
            uint32_t off = (uint32_t)(tid * 16 + q * 4096);
            CP_ASYNC16(swbase + off, wsrc + off);
        }
    }
    {
        const __half* gsrc = A + (size_t)(m0 + frow) * DD + fhalf * 32;
        uint32_t sdst = sbase + (uint32_t)(frow * SA_STRIDE + fhalf * 32) * 2;
#pragma unroll
        for (int q = 0; q < 4; q++)
            CP_ASYNC16(sdst + q * 16, (const char*)(gsrc + q * 8));
    }
    CP_COMMIT();
    // ---- group 1: A chunk 1 ----
    {
        const __half* gsrc = A + (size_t)(m0 + frow) * DD + 64 + fhalf * 32;
        uint32_t sdst = sbase + (uint32_t)(SA_CHUNK + frow * SA_STRIDE + fhalf * 32) * 2;
#pragma unroll
        for (int q = 0; q < 4; q++)
            CP_ASYNC16(sdst + q * 16, (const char*)(gsrc + q * 8));
    }
    CP_COMMIT();

#pragma unroll 1
    for (int c = 0; c < 2; c++) {
        if (c == 0) CP_WAIT(1); else CP_WAIT(0);
        __syncthreads();
        uint32_t sA_u = sbase + (uint32_t)c * SA_CHUNK * 2;

#pragma unroll
        for (int ss = 0; ss < 4; ss++) {
            int s = c * 4 + ss;
            int k0 = ss * 16;
            uint32_t Ah[2][4];
#pragma unroll
            for (int mt = 0; mt < 2; mt++) {
                uint32_t row = (uint32_t)(wm * 32 + mt * 16 + (g & 1) * 8 + ri);
                uint32_t byo = (row * SA_STRIDE + (uint32_t)(k0 + (g >> 1) * 8)) * 2;
                LDM_X4(Ah[mt], sA_u + byo);
            }
            // groups of 4 n-tiles: W from SMEM (LDS.64), 8 independent MMAs
#pragma unroll
            for (int g4 = 0; g4 < 2; g4++) {
                uint2 wv[4];
#pragma unroll
                for (int q = 0; q < 4; q++) {
                    int jj = wn * 8 + g4 * 4 + q;   // 0..15 within half
                    uint32_t off = (uint32_t)(((jj * 8 + s) << 5) + lane) * 8;
                    asm volatile("ld.shared.v2.u32 {%0,%1}, [%2];"
                        : "=r"(wv[q].x), "=r"(wv[q].y) : "r"(swbase + off));
                }
#pragma unroll
                for (int q = 0; q < 4; q++) {
                    int nt = g4 * 4 + q;
                    MMA_F16(acc[0][nt], wv[q].x, wv[q].y, Ah[0]);
                    MMA_F16(acc[1][nt], wv[q].x, wv[q].y, Ah[1]);
                }
            }
        }
        if (c == 0) __syncthreads();
    }

    // epilogue: y-half (blockIdx.y==0) -> fp16, z-half -> fp32; no bias
    int r_in = lane >> 2;
    int n_in = (lane & 3) * 2;
    bool isY = (blockIdx.y == 0);
#pragma unroll
    for (int nt = 0; nt < 8; nt++) {
        int n = wn * 64 + nt * 8 + n_in;   // 0..127 within half
#pragma unroll
        for (int mt = 0; mt < 2; mt++) {
            int r0 = m0 + wm * 32 + mt * 16 + r_in;
            if (r0 < NN) {
                if (isY) {
                    __half2 o = __floats2half2_rn(acc[mt][nt][0], acc[mt][nt][1]);
                    *(uint32_t*)(yB + (size_t)r0 * DD + n) = h2u(o);
                } else {
                    *(float2*)(z + (size_t)r0 * DD + n) = make_float2(acc[mt][nt][0], acc[mt][nt][1]);
                }
            }
            int r1 = r0 + 8;
            if (r1 < NN) {
                if (isY) {
                    __half2 o = __floats2half2_rn(acc[mt][nt][2], acc[mt][nt][3]);
                    *(uint32_t*)(yB + (size_t)r1 * DD + n) = h2u(o);
                } else {
                    *(float2*)(z + (size_t)r1 * DD + n) = make_float2(acc[mt][nt][2], acc[mt][nt][3]);
                }
            }
        }
    }
}

// ---------------- fused agg + epilogue: h = relu(mean_nb(Y) + Z + bias) ----------
__global__ void k_aggf(const float* __restrict__ z, const float* __restrict__ bias,
                       __half* __restrict__ outHalf, float* __restrict__ outF) {
    int w = (blockIdx.x * blockDim.x + threadIdx.x) >> 5;
    int lane = threadIdx.x & 31;
    if (w >= NN) return;
    int beg = g_rowptr[w];
    int dcnt = g_deg[w];
    int end = beg + dcnt;
    const uint2* in2 = (const uint2*)g_yB;
    float a0 = 0.f, a1 = 0.f, a2 = 0.f, a3 = 0.f;
    int e = beg;
#pragma unroll 1
    for (; e + 7 < end; e += 8) {
        int s0 = __ldg(&g_esrc[e]);
        int s1 = __ldg(&g_esrc[e + 1]);
        int s2 = __ldg(&g_esrc[e + 2]);
        int s3 = __ldg(&g_esrc[e + 3]);
        int s4 = __ldg(&g_esrc[e + 4]);
        int s5 = __ldg(&g_esrc[e + 5]);
        int s6 = __ldg(&g_esrc[e + 6]);
        int s7 = __ldg(&g_esrc[e + 7]);
        uint2 v0 = __ldg(&in2[(size_t)s0 * 32 + lane]);
        uint2 v1 = __ldg(&in2[(size_t)s1 * 32 + lane]);
        uint2 v2 = __ldg(&in2[(size_t)s2 * 32 + lane]);
        uint2 v3 = __ldg(&in2[(size_t)s3 * 32 + lane]);
        uint2 v4 = __ldg(&in2[(size_t)s4 * 32 + lane]);
        uint2 v5 = __ldg(&in2[(size_t)s5 * 32 + lane]);
        uint2 v6 = __ldg(&in2[(size_t)s6 * 32 + lane]);
        uint2 v7 = __ldg(&in2[(size_t)s7 * 32 + lane]);
#pragma unroll
        for (int q = 0; q < 8; q++) {
            uint2 v = q == 0 ? v0 : q == 1 ? v1 : q == 2 ? v2 : q == 3 ? v3
                    : q == 4 ? v4 : q == 5 ? v5 : q == 6 ? v6 : v7;
            float2 p0 = __half22float2(*(__half2*)&v.x);
            float2 p1 = __half22float2(*(__half2*)&v.y);
            a0 += p0.x; a1 += p0.y; a2 += p1.x; a3 += p1.y;
        }
    }
    for (; e < end; e++) {
        int s0 = __ldg(&g_esrc[e]);
        uint2 v = __ldg(&in2[(size_t)s0 * 32 + lane]);
        float2 p0 = __half22float2(*(__half2*)&v.x);
        float2 p1 = __half22float2(*(__half2*)&v.y);
        a0 += p0.x; a1 += p0.y; a2 += p1.x; a3 += p1.y;
    }
    float inv = (dcnt > 0) ? 1.0f / (float)dcnt : 0.0f;
    float4 zz = ((const float4*)z)[w * 32 + lane];
    float4 bb = ((const float4*)bias)[lane];
    float f0 = fmaxf(a0 * inv + zz.x + bb.x, 0.f);
    float f1 = fmaxf(a1 * inv + zz.y + bb.y, 0.f);
    float f2 = fmaxf(a2 * inv + zz.z + bb.z, 0.f);
    float f3 = fmaxf(a3 * inv + zz.w + bb.w, 0.f);
    if (outF) {
        ((float4*)outF)[w * 32 + lane] = make_float4(f0, f1, f2, f3);
    } else {
        __half2 h01 = __floats2half2_rn(f0, f1);
        __half2 h23 = __floats2half2_rn(f2, f3);
        ((uint2*)outHalf)[w * 32 + lane] = make_uint2(h2u(h01), h2u(h23));
    }
}

// ---------------- global add pool (batch is sorted, int32) ----------------
#define NPB 256
__global__ void k_pool(const float* __restrict__ h, const int* __restrict__ batch) {
    int t = threadIdx.x;
    int start = blockIdx.x * NPB;
    int end = start + NPB; if (end > NN) end = NN;
    if (start >= NN) return;
    int cur = batch[start];
    float sum = 0.f;
    for (int i = start; i < end; i++) {
        int b = __ldg(&batch[i]);
        if (b != cur) {
            atomicAdd(&g_pool[cur * DD + t], sum);
            sum = 0.f; cur = b;
        }
        sum += h[(size_t)i * DD + t];
    }
    atomicAdd(&g_pool[cur * DD + t], sum);
}

// ---------------- LayerNorm + final linear + scratch re-zero ----------------
__global__ void k_final(const float* __restrict__ ln_g, const float* __restrict__ ln_b,
                        const float* __restrict__ Wlin, const float* __restrict__ blin,
                        float* __restrict__ out) {
    int gtid = blockIdx.x * blockDim.x + threadIdx.x;
    int w = gtid >> 5;
    int lane = threadIdx.x & 31;
    if (w < NG) {
        float4 v = ((const float4*)g_pool)[w * 32 + lane];
        float s = v.x + v.y + v.z + v.w;
#pragma unroll
        for (int o = 16; o; o >>= 1) s += __shfl_xor_sync(0xffffffffu, s, o);
        float mean = s * (1.0f / 128.0f);
        float dx = v.x - mean, dy = v.y - mean, dz = v.z - mean, dw = v.w - mean;
        float q = dx * dx + dy * dy + dz * dz + dw * dw;
#pragma unroll
        for (int o = 16; o; o >>= 1) q += __shfl_xor_sync(0xffffffffu, q, o);
        float var = q * (1.0f / 128.0f);
        float r = rsqrtf(var + 1e-5f);
        float4 gg = ((const float4*)ln_g)[lane];
        float4 bb = ((const float4*)ln_b)[lane];
        float n0 = dx * r * gg.x + bb.x;
        float n1 = dy * r * gg.y + bb.y;
        float n2 = dz * r * gg.z + bb.z;
        float n3 = dw * r * gg.w + bb.w;
        float4 w0 = ((const float4*)Wlin)[lane];
        float4 w1 = ((const float4*)Wlin)[32 + lane];
        float d0 = n0 * w0.x + n1 * w0.y + n2 * w0.z + n3 * w0.w;
        float d1 = n0 * w1.x + n1 * w1.y + n2 * w1.z + n3 * w1.w;
#pragma unroll
        for (int o = 16; o; o >>= 1) {
            d0 += __shfl_xor_sync(0xffffffffu, d0, o);
            d1 += __shfl_xor_sync(0xffffffffu, d1, o);
        }
        if (lane == 0) {
            out[w * 2 + 0] = d0 + blin[0];
            out[w * 2 + 1] = d1 + blin[1];
        }
        ((float4*)g_pool)[w * 32 + lane] = make_float4(0.f, 0.f, 0.f, 0.f);
    }
    if (gtid == 0) g_alloc = 0;
    for (int i = gtid; i < NN; i += NG * 32) { g_deg[i] = 0; g_cursor[i] = 0; }
}

// ---------------- launch ----------------
extern "C" void kernel_launch(void* const* d_in, const int* in_sizes, int n_in,
                              void* d_out, int out_size) {
    const float* x     = (const float*)d_in[0];
    const int*   ei    = (const int*)d_in[1];
    const int*   bat   = (const int*)d_in[2];
    const float* W1l   = (const float*)d_in[3];
    const float* b1l   = (const float*)d_in[4];
    const float* W1r   = (const float*)d_in[5];
    const float* W2l   = (const float*)d_in[6];
    const float* b2l   = (const float*)d_in[7];
    const float* W2r   = (const float*)d_in[8];
    const float* ln_g  = (const float*)d_in[9];
    const float* ln_b  = (const float*)d_in[10];
    const float* Wlin  = (const float*)d_in[11];
    const float* blin  = (const float*)d_in[12];

    const int* src = ei;
    const int* dst = ei + NE;

    __half *xA, *hA, *yB;
    float *z, *h2;
    uint2* wf;
    cudaGetSymbolAddress((void**)&xA, g_xA);
    cudaGetSymbolAddress((void**)&hA, g_hA);
    cudaGetSymbolAddress((void**)&yB, g_yB);
    cudaGetSymbolAddress((void**)&z,  g_z);
    cudaGetSymbolAddress((void**)&h2, g_h2);
    cudaGetSymbolAddress((void**)&wf, g_Wf);

    cudaFuncSetAttribute(k_gemm, cudaFuncAttributeMaxDynamicSharedMemorySize, SMEM_GEMM);

    int degblks = (NE + 255) / 256;
    k_prep_deg<<<PREP_XB_BLKS + PREP_WF_BLKS + degblks, 256>>>(x, W1l, W1r, W2l, W2r, dst);  // 0
    k_alloc<<<NB_SCAN, 256>>>();                                                              // 1
    k_scatter<<<degblks, 256>>>(src, dst);                                                    // 2

    const int LSTRIDE = 32 * 8 * 32;   // uint2 per layer
    dim3 ggrid((NN + 127) / 128, 2);
    k_gemm<<<ggrid, 256, SMEM_GEMM>>>(xA, wf, yB, z);                                         // 3 (profiled)
    k_aggf<<<(NN * 32 + 255) / 256, 256>>>(z, b1l, hA, (float*)nullptr);                      // 4
    k_gemm<<<ggrid, 256, SMEM_GEMM>>>(hA, wf + LSTRIDE, yB, z);                               // 5
    k_aggf<<<(NN * 32 + 255) / 256, 256>>>(z, b2l, (__half*)nullptr, h2);                     // 6

    k_pool<<<(NN + NPB - 1) / NPB, 128>>>(h2, bat);                                           // 7
    k_final<<<(NG * 32 + 255) / 256, 256>>>(ln_g, ln_b, Wlin, blin, (float*)d_out);           // 8
}